// round 1
// baseline (speedup 1.0000x reference)
#include <cuda_runtime.h>

// LIF forward: X[B=128, T=32, N=8192] fp32 -> spikes fp32 (same shape).
// Per (b, n): mem_{t} = mem_{t-1} + (x_t - mem_{t-1})/TAU ; spike = mem > 1 ;
// mem = 0 where spiked. TAU=2, V_RESET=0, V_TH=1.
//
// Pure HBM-streaming kernel: one thread owns 4 consecutive n (float4),
// walks t with stride N/4. Fully unrolled so ptxas batches the 32
// independent loads for MLP.

static constexpr int B = 128;
static constexpr int T = 32;
static constexpr int N = 8192;
static constexpr int N4 = N / 4;          // float4 columns
static constexpr int TOTAL4 = B * N4;     // total float4 lanes = 262144

__global__ __launch_bounds__(256) void lif_kernel(const float4* __restrict__ X,
                                                  float4* __restrict__ out) {
    int idx = blockIdx.x * blockDim.x + threadIdx.x;  // 0 .. TOTAL4-1
    if (idx >= TOTAL4) return;

    int b = idx / N4;
    int n4 = idx - b * N4;

    const float4* xp = X + (size_t)b * T * N4 + n4;
    float4* op = out + (size_t)b * T * N4 + n4;

    float m0 = 0.f, m1 = 0.f, m2 = 0.f, m3 = 0.f;

#pragma unroll
    for (int t = 0; t < T; t++) {
        float4 x = xp[(size_t)t * N4];

        // leaky integrate (match reference rounding: mem += (x - mem)*0.5)
        m0 = m0 + (x.x - m0) * 0.5f;
        m1 = m1 + (x.y - m1) * 0.5f;
        m2 = m2 + (x.z - m2) * 0.5f;
        m3 = m3 + (x.w - m3) * 0.5f;

        float4 s;
        s.x = (m0 > 1.0f) ? 1.0f : 0.0f;
        s.y = (m1 > 1.0f) ? 1.0f : 0.0f;
        s.z = (m2 > 1.0f) ? 1.0f : 0.0f;
        s.w = (m3 > 1.0f) ? 1.0f : 0.0f;

        // hard reset to 0 where spiked
        if (s.x != 0.0f) m0 = 0.0f;
        if (s.y != 0.0f) m1 = 0.0f;
        if (s.z != 0.0f) m2 = 0.0f;
        if (s.w != 0.0f) m3 = 0.0f;

        op[(size_t)t * N4] = s;
    }
}

extern "C" void kernel_launch(void* const* d_in, const int* in_sizes, int n_in,
                              void* d_out, int out_size) {
    const float4* X = (const float4*)d_in[0];
    float4* out = (float4*)d_out;
    int blocks = (TOTAL4 + 255) / 256;
    lif_kernel<<<blocks, 256>>>(X, out);
}